// round 12
// baseline (speedup 1.0000x reference)
#include <cuda_runtime.h>

typedef unsigned long long u64;

#define NL    19
#define DIM   6
#define LANES 2                 // packed f32x2 lanes per thread
#define ROWS  (2 * LANES)       // 4 rows per thread
#define TPB   128

// ---------------- packed f32x2 helpers (Blackwell sm_103a) ----------------
__device__ __forceinline__ u64 fma2(u64 a, u64 b, u64 c) {
    u64 d; asm("fma.rn.f32x2 %0, %1, %2, %3;" : "=l"(d) : "l"(a), "l"(b), "l"(c)); return d;
}
__device__ __forceinline__ u64 add2(u64 a, u64 b) {
    u64 d; asm("add.rn.f32x2 %0, %1, %2;" : "=l"(d) : "l"(a), "l"(b)); return d;
}
__device__ __forceinline__ u64 pack2(float x, float y) {
    u64 d; asm("mov.b64 %0, {%1, %2};" : "=l"(d) : "f"(x), "f"(y)); return d;
}
__device__ __forceinline__ void unpack2(u64 v, float &x, float &y) {
    asm("mov.b64 {%0, %1}, %2;" : "=f"(x), "=f"(y) : "l"(v));
}

// ---------------- constant-bank weight storage ----------------
struct Consts {
    u64 W[NL][DIM * DIM];   // packed {w,w}
    u64 B[NL][DIM];         // packed {b,b}
    u64 scale[DIM], off[DIM];
};
__device__   Consts g_stage;    // staging (written by prep kernel)
__constant__ Consts c_c;        // read via const port

__global__ void prep_kernel(const float* __restrict__ Ws,
                            const float* __restrict__ bs,
                            const float* __restrict__ bounds)
{
    int i = threadIdx.x + blockIdx.x * blockDim.x;
    if (i < NL * DIM * DIM) {
        float w = Ws[i];
        g_stage.W[i / (DIM * DIM)][i % (DIM * DIM)] = pack2(w, w);
    }
    if (i < NL * DIM) {
        float b = bs[i];
        g_stage.B[i / DIM][i % DIM] = pack2(b, b);
    }
    if (i < DIM) {
        float lo = bounds[2 * i];
        float hi = bounds[2 * i + 1];
        float s  = 1.0f / (hi - lo);
        float o  = -lo * s;
        g_stage.scale[i] = pack2(s, s);
        g_stage.off[i]   = pack2(o, o);
    }
}

__global__ void __launch_bounds__(TPB, 6)     // 80 regs -> 24 warps/SM (R10 frontier)
mlp_kernel(const float* __restrict__ X,
           float* __restrict__ out,
           int B)
{
    // shared copy of the k>=3 half of each weight row: port-split vs const bank
    __shared__ __align__(16) u64 sW[NL][DIM][DIM / 2];   // [layer][j][k-3]
    // residual parking (SoA, conflict-free 64-bit lanes)
    __shared__ u64 sRes[LANES * DIM][TPB];

    // fill shared weight half from the (already packed) constant image is not
    // possible before c_c is valid on first graph launch order; copy from gmem
    // staging instead would race. Fill from c_c is fine: memcpy node precedes
    // this kernel in the same stream.
    for (int i = threadIdx.x; i < NL * DIM * (DIM / 2); i += blockDim.x) {
        int L = i / (DIM * (DIM / 2));
        int r = i % (DIM * (DIM / 2));
        int j = r / (DIM / 2);
        int k = r % (DIM / 2);
        sW[L][j][k] = c_c.W[L][j * DIM + 3 + k];
    }
    __syncthreads();

    long long tid  = (long long)blockIdx.x * blockDim.x + threadIdx.x;
    long long base = tid * ROWS;
    if (base >= B) return;
    const int lt = threadIdx.x;

    // LIN: k=0..2 weights from const port, k=3..5 from shared port, bias const.
#define LIN(L, IN, OUT) do {                                                   \
    _Pragma("unroll")                                                          \
    for (int j = 0; j < DIM; j++) {                                            \
        u64 acc[LANES];                                                        \
        u64 bb = c_c.B[(L)][j];                                                \
        _Pragma("unroll")                                                      \
        for (int p = 0; p < LANES; p++) acc[p] = bb;                           \
        _Pragma("unroll")                                                      \
        for (int k = 0; k < 3; k++) {                                          \
            u64 ww = c_c.W[(L)][j * DIM + k];                                  \
            _Pragma("unroll")                                                  \
            for (int p = 0; p < LANES; p++) acc[p] = fma2(IN[p][k], ww, acc[p]);\
        }                                                                      \
        _Pragma("unroll")                                                      \
        for (int k = 3; k < DIM; k++) {                                        \
            u64 ww = sW[(L)][j][k - 3];                                        \
            _Pragma("unroll")                                                  \
            for (int p = 0; p < LANES; p++) acc[p] = fma2(IN[p][k], ww, acc[p]);\
        }                                                                      \
        _Pragma("unroll")                                                      \
        for (int p = 0; p < LANES; p++) OUT[p][j] = acc[p];                    \
    } } while (0)

    // lrelu per half: FMUL-imm (fma pipe, rt=1) + FMNMX (alu pipe)
#define LRELU(A) do {                                                          \
    _Pragma("unroll")                                                          \
    for (int p = 0; p < LANES; p++) {                                          \
        _Pragma("unroll")                                                      \
        for (int j = 0; j < DIM; j++) {                                        \
            float lo_, hi_;                                                    \
            unpack2(A[p][j], lo_, hi_);                                        \
            lo_ = fmaxf(lo_, 0.01f * lo_);                                     \
            hi_ = fmaxf(hi_, 0.01f * hi_);                                     \
            A[p][j] = pack2(lo_, hi_);                                         \
        }                                                                      \
    } } while (0)

    if (base + ROWS <= B) {
        // ---------- fast path: 4 full rows ----------
        u64 w[LANES][DIM], t[LANES][DIM];

        const float4* Xv = reinterpret_cast<const float4*>(X + base * DIM);
#pragma unroll
        for (int p = 0; p < LANES; p++) {
            float4 q0 = Xv[3 * p + 0], q1 = Xv[3 * p + 1], q2 = Xv[3 * p + 2];
            w[p][0] = fma2(pack2(q0.x, q1.z), c_c.scale[0], c_c.off[0]);
            w[p][1] = fma2(pack2(q0.y, q1.w), c_c.scale[1], c_c.off[1]);
            w[p][2] = fma2(pack2(q0.z, q2.x), c_c.scale[2], c_c.off[2]);
            w[p][3] = fma2(pack2(q0.w, q2.y), c_c.scale[3], c_c.off[3]);
            w[p][4] = fma2(pack2(q1.x, q2.z), c_c.scale[4], c_c.off[4]);
            w[p][5] = fma2(pack2(q1.y, q2.w), c_c.scale[5], c_c.off[5]);
        }

#pragma unroll
        for (int blk = 0; blk < 4; blk++) {
            const int i0 = blk * 4;
#pragma unroll
            for (int p = 0; p < LANES; p++)
#pragma unroll
                for (int j = 0; j < DIM; j++) sRes[p * DIM + j][lt] = w[p][j];

            LIN(i0 + 0, w, t); LRELU(t);
            LIN(i0 + 1, t, w); LRELU(w);
            LIN(i0 + 2, w, t); LRELU(t);
            LIN(i0 + 3, t, w);
#pragma unroll
            for (int p = 0; p < LANES; p++)
#pragma unroll
                for (int j = 0; j < DIM; j++)
                    w[p][j] = add2(w[p][j], sRes[p * DIM + j][lt]);
        }
        LIN(16, w, t); LRELU(t);
        LIN(17, t, w); LRELU(w);
        LIN(18, w, t);

        float4* Ov = reinterpret_cast<float4*>(out + base * DIM);
#pragma unroll
        for (int p = 0; p < LANES; p++) {
            float a0, b0, a1, b1, a2, b2, a3, b3, a4, b4, a5, b5;
            unpack2(t[p][0], a0, b0); unpack2(t[p][1], a1, b1);
            unpack2(t[p][2], a2, b2); unpack2(t[p][3], a3, b3);
            unpack2(t[p][4], a4, b4); unpack2(t[p][5], a5, b5);
            Ov[3 * p + 0] = make_float4(a0, a1, a2, a3);
            Ov[3 * p + 1] = make_float4(a4, a5, b0, b1);
            Ov[3 * p + 2] = make_float4(b2, b3, b4, b5);
        }
    } else {
        // ---------- tail path: scalar per-row (not taken when B%4==0) ----------
        for (long long r = base; r < B; r++) {
            float x[DIM], y[DIM], rs[DIM];
            for (int k = 0; k < DIM; k++) {
                float s, o, dummy;
                unpack2(c_c.scale[k], s, dummy);
                unpack2(c_c.off[k],   o, dummy);
                x[k] = X[r * DIM + k] * s + o;
            }

            auto lin_s = [&](int L, const float* in, float* o) {
                for (int j = 0; j < DIM; j++) {
                    float a, d0;
                    unpack2(c_c.B[L][j], a, d0);
                    for (int k = 0; k < DIM; k++) {
                        float wv, d1;
                        unpack2(c_c.W[L][j * DIM + k], wv, d1);
                        a = fmaf(in[k], wv, a);
                    }
                    o[j] = a;
                }
            };
            auto lrelu_s = [&](float* v) {
                for (int j = 0; j < DIM; j++) v[j] = fmaxf(v[j], 0.01f * v[j]);
            };

            for (int blk = 0; blk < 4; blk++) {
                int i0 = blk * 4;
                for (int k = 0; k < DIM; k++) rs[k] = x[k];
                lin_s(i0 + 0, x, y); lrelu_s(y);
                lin_s(i0 + 1, y, x); lrelu_s(x);
                lin_s(i0 + 2, x, y); lrelu_s(y);
                lin_s(i0 + 3, y, x);
                for (int k = 0; k < DIM; k++) x[k] += rs[k];
            }
            lin_s(16, x, y); lrelu_s(y);
            lin_s(17, y, x); lrelu_s(x);
            lin_s(18, x, y);
            for (int k = 0; k < DIM; k++) out[r * DIM + k] = y[k];
        }
    }
#undef LIN
#undef LRELU
}

extern "C" void kernel_launch(void* const* d_in, const int* in_sizes, int n_in,
                              void* d_out, int out_size)
{
    const float* X      = (const float*)d_in[0];
    const float* Ws     = (const float*)d_in[1];
    const float* bs     = (const float*)d_in[2];
    const float* bounds = (const float*)d_in[3];
    float* out = (float*)d_out;

    int B = in_sizes[0] / DIM;

    // 1) pack weights into staging struct (device global, no alloc)
    prep_kernel<<<3, 256>>>(Ws, bs, bounds);

    // 2) staging -> constant bank (D2D memcpy node, graph-capturable)
    void* stage_ptr = nullptr;
    cudaGetSymbolAddress(&stage_ptr, g_stage);
    cudaMemcpyToSymbolAsync(c_c, stage_ptr, sizeof(Consts), 0,
                            cudaMemcpyDeviceToDevice, 0);

    // 3) main kernel
    long long tiles = ((long long)B + ROWS - 1) / ROWS;
    int blocks = (int)((tiles + TPB - 1) / TPB);
    mlp_kernel<<<blocks, TPB>>>(X, out, B);
}

// round 14
// speedup vs baseline: 1.4246x; 1.4246x over previous
#include <cuda_runtime.h>

typedef unsigned long long u64;

#define NL    19
#define DIM   6
#define LANES 2                 // packed f32x2 lanes per thread
#define ROWS  (2 * LANES)       // 4 rows per thread
#define TPB   128

// ---------------- packed f32x2 helpers (Blackwell sm_103a) ----------------
__device__ __forceinline__ u64 fma2(u64 a, u64 b, u64 c) {
    u64 d; asm("fma.rn.f32x2 %0, %1, %2, %3;" : "=l"(d) : "l"(a), "l"(b), "l"(c)); return d;
}
__device__ __forceinline__ u64 add2(u64 a, u64 b) {
    u64 d; asm("add.rn.f32x2 %0, %1, %2;" : "=l"(d) : "l"(a), "l"(b)); return d;
}
__device__ __forceinline__ u64 pack2(float x, float y) {
    u64 d; asm("mov.b64 %0, {%1, %2};" : "=l"(d) : "f"(x), "f"(y)); return d;
}
__device__ __forceinline__ void unpack2(u64 v, float &x, float &y) {
    asm("mov.b64 {%0, %1}, %2;" : "=f"(x), "=f"(y) : "l"(v));
}

// ---------------- constant-bank weight storage ----------------
struct Consts {
    u64 W[NL][DIM * DIM];   // packed {w,w}; 16B-aligned pairs
    u64 B[NL][DIM];         // packed {b,b}; 16B-aligned pairs
    u64 scale[DIM], off[DIM];
};
__device__   Consts g_stage;    // staging (written by prep kernel)
__constant__ Consts c_c;        // read via const port

__global__ void prep_kernel(const float* __restrict__ Ws,
                            const float* __restrict__ bs,
                            const float* __restrict__ bounds)
{
    int i = threadIdx.x + blockIdx.x * blockDim.x;
    if (i < NL * DIM * DIM) {
        float w = Ws[i];
        g_stage.W[i / (DIM * DIM)][i % (DIM * DIM)] = pack2(w, w);
    }
    if (i < NL * DIM) {
        float b = bs[i];
        g_stage.B[i / DIM][i % DIM] = pack2(b, b);
    }
    if (i < DIM) {
        float lo = bounds[2 * i];
        float hi = bounds[2 * i + 1];
        float s  = 1.0f / (hi - lo);
        float o  = -lo * s;
        g_stage.scale[i] = pack2(s, s);
        g_stage.off[i]   = pack2(o, o);
    }
}

__global__ void __launch_bounds__(TPB, 6)     // ~80 regs -> 24 warps/SM (R10 frontier)
mlp_kernel(const float* __restrict__ X,
           float* __restrict__ out,
           int B)
{
    // residual parking in shared (SoA, conflict-free 64-bit lanes); L1 is idle
    __shared__ u64 sRes[LANES * DIM][TPB];

    long long tid  = (long long)blockIdx.x * blockDim.x + threadIdx.x;
    long long base = tid * ROWS;
    if (base >= B) return;
    const int lt = threadIdx.x;

    // LIN over output-neuron pairs; const reads vectorized (ld.const.v2.u64):
    // 21 const loads/layer instead of 42.
#define LIN(L, IN, OUT) do {                                                    \
    _Pragma("unroll")                                                           \
    for (int j = 0; j < DIM; j += 2) {                                          \
        ulonglong2 bb = *reinterpret_cast<const ulonglong2*>(&c_c.B[(L)][j]);   \
        u64 a0[LANES], a1[LANES];                                               \
        _Pragma("unroll")                                                       \
        for (int p = 0; p < LANES; p++) { a0[p] = bb.x; a1[p] = bb.y; }         \
        _Pragma("unroll")                                                       \
        for (int kk = 0; kk < DIM; kk += 2) {                                   \
            ulonglong2 w0 = *reinterpret_cast<const ulonglong2*>(               \
                                &c_c.W[(L)][j * DIM + kk]);                     \
            ulonglong2 w1 = *reinterpret_cast<const ulonglong2*>(               \
                                &c_c.W[(L)][(j + 1) * DIM + kk]);               \
            _Pragma("unroll")                                                   \
            for (int p = 0; p < LANES; p++) {                                   \
                a0[p] = fma2(IN[p][kk],     w0.x, a0[p]);                       \
                a0[p] = fma2(IN[p][kk + 1], w0.y, a0[p]);                       \
                a1[p] = fma2(IN[p][kk],     w1.x, a1[p]);                       \
                a1[p] = fma2(IN[p][kk + 1], w1.y, a1[p]);                       \
            }                                                                   \
        }                                                                       \
        _Pragma("unroll")                                                       \
        for (int p = 0; p < LANES; p++) { OUT[p][j] = a0[p]; OUT[p][j+1] = a1[p]; } \
    } } while (0)

    // lrelu per half: FMUL-imm (fma pipe, rt=1) + FMNMX (alu pipe)
#define LRELU(A) do {                                                          \
    _Pragma("unroll")                                                          \
    for (int p = 0; p < LANES; p++) {                                          \
        _Pragma("unroll")                                                      \
        for (int j = 0; j < DIM; j++) {                                        \
            float lo_, hi_;                                                    \
            unpack2(A[p][j], lo_, hi_);                                        \
            lo_ = fmaxf(lo_, 0.01f * lo_);                                     \
            hi_ = fmaxf(hi_, 0.01f * hi_);                                     \
            A[p][j] = pack2(lo_, hi_);                                         \
        }                                                                      \
    } } while (0)

    if (base + ROWS <= B) {
        // ---------- fast path: 4 full rows ----------
        u64 w[LANES][DIM], t[LANES][DIM];

        const float4* Xv = reinterpret_cast<const float4*>(X + base * DIM);
#pragma unroll
        for (int p = 0; p < LANES; p++) {
            float4 q0 = Xv[3 * p + 0], q1 = Xv[3 * p + 1], q2 = Xv[3 * p + 2];
            w[p][0] = fma2(pack2(q0.x, q1.z), c_c.scale[0], c_c.off[0]);
            w[p][1] = fma2(pack2(q0.y, q1.w), c_c.scale[1], c_c.off[1]);
            w[p][2] = fma2(pack2(q0.z, q2.x), c_c.scale[2], c_c.off[2]);
            w[p][3] = fma2(pack2(q0.w, q2.y), c_c.scale[3], c_c.off[3]);
            w[p][4] = fma2(pack2(q1.x, q2.z), c_c.scale[4], c_c.off[4]);
            w[p][5] = fma2(pack2(q1.y, q2.w), c_c.scale[5], c_c.off[5]);
        }

#pragma unroll
        for (int blk = 0; blk < 4; blk++) {
            const int i0 = blk * 4;
#pragma unroll
            for (int p = 0; p < LANES; p++)
#pragma unroll
                for (int j = 0; j < DIM; j++) sRes[p * DIM + j][lt] = w[p][j];

            LIN(i0 + 0, w, t); LRELU(t);
            LIN(i0 + 1, t, w); LRELU(w);
            LIN(i0 + 2, w, t); LRELU(t);
            LIN(i0 + 3, t, w);
#pragma unroll
            for (int p = 0; p < LANES; p++)
#pragma unroll
                for (int j = 0; j < DIM; j++)
                    w[p][j] = add2(w[p][j], sRes[p * DIM + j][lt]);
        }
        LIN(16, w, t); LRELU(t);
        LIN(17, t, w); LRELU(w);
        LIN(18, w, t);

        float4* Ov = reinterpret_cast<float4*>(out + base * DIM);
#pragma unroll
        for (int p = 0; p < LANES; p++) {
            float a0, b0, a1, b1, a2, b2, a3, b3, a4, b4, a5, b5;
            unpack2(t[p][0], a0, b0); unpack2(t[p][1], a1, b1);
            unpack2(t[p][2], a2, b2); unpack2(t[p][3], a3, b3);
            unpack2(t[p][4], a4, b4); unpack2(t[p][5], a5, b5);
            Ov[3 * p + 0] = make_float4(a0, a1, a2, a3);
            Ov[3 * p + 1] = make_float4(a4, a5, b0, b1);
            Ov[3 * p + 2] = make_float4(b2, b3, b4, b5);
        }
    } else {
        // ---------- tail path: scalar per-row (not taken when B%4==0) ----------
        for (long long r = base; r < B; r++) {
            float x[DIM], y[DIM], rs[DIM];
            for (int k = 0; k < DIM; k++) {
                float s, o, dummy;
                unpack2(c_c.scale[k], s, dummy);
                unpack2(c_c.off[k],   o, dummy);
                x[k] = X[r * DIM + k] * s + o;
            }

            auto lin_s = [&](int L, const float* in, float* o) {
                for (int j = 0; j < DIM; j++) {
                    float a, d0;
                    unpack2(c_c.B[L][j], a, d0);
                    for (int k = 0; k < DIM; k++) {
                        float wv, d1;
                        unpack2(c_c.W[L][j * DIM + k], wv, d1);
                        a = fmaf(in[k], wv, a);
                    }
                    o[j] = a;
                }
            };
            auto lrelu_s = [&](float* v) {
                for (int j = 0; j < DIM; j++) v[j] = fmaxf(v[j], 0.01f * v[j]);
            };

            for (int blk = 0; blk < 4; blk++) {
                int i0 = blk * 4;
                for (int k = 0; k < DIM; k++) rs[k] = x[k];
                lin_s(i0 + 0, x, y); lrelu_s(y);
                lin_s(i0 + 1, y, x); lrelu_s(x);
                lin_s(i0 + 2, x, y); lrelu_s(y);
                lin_s(i0 + 3, y, x);
                for (int k = 0; k < DIM; k++) x[k] += rs[k];
            }
            lin_s(16, x, y); lrelu_s(y);
            lin_s(17, y, x); lrelu_s(x);
            lin_s(18, x, y);
            for (int k = 0; k < DIM; k++) out[r * DIM + k] = y[k];
        }
    }
#undef LIN
#undef LRELU
}

extern "C" void kernel_launch(void* const* d_in, const int* in_sizes, int n_in,
                              void* d_out, int out_size)
{
    const float* X      = (const float*)d_in[0];
    const float* Ws     = (const float*)d_in[1];
    const float* bs     = (const float*)d_in[2];
    const float* bounds = (const float*)d_in[3];
    float* out = (float*)d_out;

    int B = in_sizes[0] / DIM;

    // 1) pack weights into staging struct (device global, no alloc)
    prep_kernel<<<3, 256>>>(Ws, bs, bounds);

    // 2) staging -> constant bank (D2D memcpy node, graph-capturable)
    void* stage_ptr = nullptr;
    cudaGetSymbolAddress(&stage_ptr, g_stage);
    cudaMemcpyToSymbolAsync(c_c, stage_ptr, sizeof(Consts), 0,
                            cudaMemcpyDeviceToDevice, 0);

    // 3) main kernel
    long long tiles = ((long long)B + ROWS - 1) / ROWS;
    int blocks = (int)((tiles + TPB - 1) / TPB);
    mlp_kernel<<<blocks, TPB>>>(X, out, B);
}